// round 9
// baseline (speedup 1.0000x reference)
#include <cuda_runtime.h>
#include <math.h>

#define BATCH 4
#define DIMC  64
#define HFC   128
#define C2C   256
#define HH    256
#define WWC   256
#define HW    (HH*WWC)   // 65536

typedef unsigned int u32;
typedef unsigned long long u64;

// ---------------- scratch (device globals: allocation-free rule) -------------
__device__ float  g_u[(size_t)BATCH*C2C*HW];          // spectral output (268 MB)
__device__ float  g_g[(size_t)BATCH*HFC*HW];          // gated output    (134 MB)
__device__ float2 g_bf[(size_t)C2C*8*8*32];           // conv-G B-fragments (4 MB)
__device__ u64    g_wo[128*32];                       // packed w_out for K4

// ---------------- helpers ----------------------------------------------------
__device__ __forceinline__ u32 tf32b(float x){
    u32 r; asm("cvt.rna.tf32.f32 %0, %1;" : "=r"(r) : "f"(x)); return r;
}
__device__ __forceinline__ float tf32f(float x){ return __uint_as_float(tf32b(x)); }
__device__ __forceinline__ u32 bits(float x){ return __float_as_uint(x); }

__device__ __forceinline__ void mma8(float* d, u32 a0,u32 a1,u32 a2,u32 a3, u32 b0,u32 b1){
    asm("mma.sync.aligned.m16n8k8.row.col.f32.tf32.tf32.f32 "
        "{%0,%1,%2,%3},{%4,%5,%6,%7},{%8,%9},{%0,%1,%2,%3};"
        : "+f"(d[0]),"+f"(d[1]),"+f"(d[2]),"+f"(d[3])
        : "r"(a0),"r"(a1),"r"(a2),"r"(a3),"r"(b0),"r"(b1));
}

__device__ __forceinline__ u64 pk(float lo, float hi){
    u64 r; asm("mov.b64 %0, {%1,%2};" : "=l"(r) : "f"(lo), "f"(hi)); return r;
}
__device__ __forceinline__ float2 upk(u64 v){
    float2 r; asm("mov.b64 {%0,%1}, %2;" : "=f"(r.x), "=f"(r.y) : "l"(v)); return r;
}
__device__ __forceinline__ void fma2(u64& d, u64 a, u64 b){
    asm("fma.rn.f32x2 %0, %1, %2, %0;" : "+l"(d) : "l"(a), "l"(b));
}

// ---------------- K0: spectral filter -> conv-G MMA B-fragments --------------
// g_c[n1,n2] = (1/64) * sum_{k1,k2} G(k1,k2) cos(pi/4*(k1*n1+k2*n2)),
// G = Hermitian extension of F with symmetrization at k2 in {0,4}
// (matches pocketfft/cuFFT c2r dropping Im at bins 0 and N/2).
// Conv matrix Gm[n][m] = g[(n1-m1)&7][(n2-m2)&7] (u = h_patch @ Gm^T).
// B-fragment (col-major K x N) for mma.m16n8k8:
//   b0(lane) = Gm[n = nt*8 + lane/4][m = kk*8 + lane%4]
//   b1(lane) = Gm[n][m+4]
__global__ void k0_spectral(const float* __restrict__ filt){
    __shared__ float gs[64];
    int c = blockIdx.x, t = threadIdx.x;
    if (t < 64){
        int n1 = t >> 3, n2 = t & 7;
        const float* F = filt + c*40;   // [8][5]
        float s = 0.f;
        for (int k1=0;k1<8;k1++){
            for (int k2=0;k2<8;k2++){
                float Gv;
                if (k2>=1 && k2<=3)      Gv = F[k1*5+k2];
                else if (k2>=5)          Gv = F[((8-k1)&7)*5 + (8-k2)];
                else                     Gv = 0.5f*(F[k1*5+k2] + F[((8-k1)&7)*5 + k2]);
                int m = (k1*n1 + k2*n2) & 7;
                s += Gv * cospif(0.25f * (float)m);
            }
        }
        gs[t] = s * (1.f/64.f);
    }
    __syncthreads();
    for (int i=t; i<2048; i+=256){
        int kk = i>>8, nt = (i>>5)&7, lane = i&31;
        int n  = nt*8 + (lane>>2);
        int m0 = kk*8 + (lane&3);
        int m1 = m0 + 4;
        int n1 = n>>3, n2 = n&7;
        float b0 = gs[ (((n1-(m0>>3))&7)<<3) | ((n2-(m0&7))&7) ];
        float b1 = gs[ (((n1-(m1>>3))&7)<<3) | ((n2-(m1&7))&7) ];
        g_bf[((size_t)(c*8+kk)*8 + nt)*32 + lane] = make_float2(tf32f(b0), tf32f(b1));
    }
}

// ---------------- K0b: pack w_out for K4 -------------------------------------
__global__ void k0_packw(const float* __restrict__ w_out){
    int idx = blockIdx.x*256 + threadIdx.x;
    if (idx < 128*32){
        int ii = idx >> 5, j = idx & 31;
        g_wo[idx] = pk(w_out[(2*j)*HFC + ii], w_out[(2*j+1)*HFC + ii]);
    }
}

// ---------------- K12: fused in-proj GEMM + spectral conv GEMM (tf32 MMA) ----
// Block: 16 output channels x (8-row x 256-col strip = 2048 px = 32 patches).
// Grid (16, 32, 4), ocg fastest for x L2 reuse.
// Phase 1: h[16 x 2048] = W[16x64] @ x[64x2048], chunked 256 px (one row) at a
//          time, D stored tf32-rounded into smem hs.
// Phase 2: per channel, u[32 patch x 64] = h_patch[32x64] @ Gm^T via mma,
//          B-fragments streamed coalesced from g_bf.
__global__ __launch_bounds__(256) void k12_fused(const float* __restrict__ x,
                                                 const float* __restrict__ w_in){
    extern __shared__ float sm[];
    float* ws = sm;                 // [16][68]   (4.3 KB)
    float* xs = sm + 16*68;         // [64][257]  (65.8 KB)
    float* hs = xs + 64*257;        // [16][2060] (131.8 KB)
    int oc0 = blockIdx.x*16;
    int s   = blockIdx.y;           // 8-row strip index (0..31)
    int b   = blockIdx.z;
    int t = threadIdx.x, lane = t & 31, w = t >> 5;
    int la = lane & 3, lq = lane >> 2;

    for (int i=t; i<16*64; i+=256){
        int o = i>>6, c = i&63;
        ws[o*68 + c] = tf32f(w_in[(oc0+o)*DIMC + c]);
    }

    const float* xb = x + (size_t)b*DIMC*HW + (size_t)s*8*WWC;
    for (int r=0; r<8; r++){
        __syncthreads();
        for (int i=t; i<64*256; i+=256){
            int c = i>>8, px = i&255;
            xs[c*257 + px] = tf32f(xb[(size_t)c*HW + r*WWC + px]);
        }
        __syncthreads();
        float d[4][4];
        #pragma unroll
        for (int nt=0;nt<4;nt++){ d[nt][0]=d[nt][1]=d[nt][2]=d[nt][3]=0.f; }
        #pragma unroll
        for (int kk=0;kk<8;kk++){
            u32 a0 = bits(ws[lq*68 + kk*8 + la]);
            u32 a1 = bits(ws[(lq+8)*68 + kk*8 + la]);
            u32 a2 = bits(ws[lq*68 + kk*8 + la + 4]);
            u32 a3 = bits(ws[(lq+8)*68 + kk*8 + la + 4]);
            #pragma unroll
            for (int nt=0;nt<4;nt++){
                int px = w*32 + nt*8 + lq;
                u32 b0 = bits(xs[(kk*8+la)*257 + px]);
                u32 b1 = bits(xs[(kk*8+la+4)*257 + px]);
                mma8(d[nt], a0,a1,a2,a3, b0,b1);
            }
        }
        // store h tile (tf32-rounded so phase-2 A operand is already tf32)
        #pragma unroll
        for (int nt=0;nt<4;nt++){
            int col = r*256 + w*32 + nt*8 + 2*la;
            *(float2*)&hs[lq*2060 + col]     = make_float2(tf32f(d[nt][0]), tf32f(d[nt][1]));
            *(float2*)&hs[(lq+8)*2060 + col] = make_float2(tf32f(d[nt][2]), tf32f(d[nt][3]));
        }
    }
    __syncthreads();

    // Phase 2: per-channel conv GEMM. warp w handles channels w*2, w*2+1.
    for (int ci=0; ci<2; ci++){
        int chl = w*2 + ci;
        float d[2][8][4];
        #pragma unroll
        for (int mt=0;mt<2;mt++)
            #pragma unroll
            for (int nt=0;nt<8;nt++){ d[mt][nt][0]=d[mt][nt][1]=d[mt][nt][2]=d[mt][nt][3]=0.f; }
        const float* hc = hs + chl*2060;
        const float2* bfc = &g_bf[(size_t)((oc0+chl)*8)*8*32 + lane];
        #pragma unroll
        for (int kk=0;kk<8;kk++){
            u32 a[2][4];
            #pragma unroll
            for (int mt=0;mt<2;mt++){
                int p0 = mt*16 + lq;
                a[mt][0] = bits(hc[kk*256 + p0*8 + la]);
                a[mt][1] = bits(hc[kk*256 + (p0+8)*8 + la]);
                a[mt][2] = bits(hc[kk*256 + p0*8 + la + 4]);
                a[mt][3] = bits(hc[kk*256 + (p0+8)*8 + la + 4]);
            }
            const float2* bfk = bfc + (size_t)kk*8*32;
            #pragma unroll
            for (int nt=0;nt<8;nt++){
                float2 bv = bfk[nt*32];
                u32 b0 = bits(bv.x), b1 = bits(bv.y);
                mma8(d[0][nt], a[0][0],a[0][1],a[0][2],a[0][3], b0,b1);
                mma8(d[1][nt], a[1][0],a[1][1],a[1][2],a[1][3], b0,b1);
            }
        }
        float* ub = g_u + (size_t)(b*C2C + oc0 + chl)*HW + (size_t)s*8*WWC;
        #pragma unroll
        for (int mt=0;mt<2;mt++){
            #pragma unroll
            for (int nt=0;nt<8;nt++){
                int p = mt*16 + lq;
                *(float2*)&ub[nt*WWC + p*8 + 2*la]     = make_float2(d[mt][nt][0], d[mt][nt][1]);
                *(float2*)&ub[nt*WWC + (p+8)*8 + 2*la] = make_float2(d[mt][nt][2], d[mt][nt][3]);
            }
        }
    }
}

// ---------------- K3: depthwise 3x3 (SAME) + exact GELU gate -----------------
__global__ __launch_bounds__(256) void k3_dwgelu(const float* __restrict__ w_dw){
    __shared__ float su[2][18][258];
    int yt = blockIdx.x, i = blockIdx.y, b = blockIdx.z;
    int t = threadIdx.x;
    int y0 = yt*16;
    const float* u1 = g_u + (size_t)(b*C2C + i)*HW;
    const float* u2 = g_u + (size_t)(b*C2C + i + HFC)*HW;
    for (int rr=0; rr<18; rr++){
        int y = y0 + rr - 1;
        bool ok = (y>=0 && y<HH);
        su[0][rr][t+1] = ok ? u1[y*WWC + t] : 0.f;
        su[1][rr][t+1] = ok ? u2[y*WWC + t] : 0.f;
    }
    if (t < 18){ su[0][t][0]=0.f; su[0][t][257]=0.f; su[1][t][0]=0.f; su[1][t][257]=0.f; }
    __syncthreads();
    float wA[9], wB[9];
    #pragma unroll
    for (int k=0;k<9;k++){ wA[k]=w_dw[i*9+k]; wB[k]=w_dw[(i+HFC)*9+k]; }
    float* gb = g_g + (size_t)(b*HFC + i)*HW;
    for (int r=0;r<16;r++){
        float d1=0.f, d2=0.f;
        #pragma unroll
        for (int dy=0;dy<3;dy++){
            #pragma unroll
            for (int dx=0;dx<3;dx++){
                d1 = fmaf(wA[dy*3+dx], su[0][r+dy][t+dx], d1);
                d2 = fmaf(wB[dy*3+dx], su[1][r+dy][t+dx], d2);
            }
        }
        float ge = 0.5f*d1*(1.f + erff(d1*0.70710678118654752f));
        gb[(y0+r)*WWC + t] = ge*d2;
    }
}

// ---------------- K4: out-projection (register-tiled FMA2 GEMM) --------------
__global__ __launch_bounds__(256) void k4_outproj(float* __restrict__ out){
    __shared__ float gs[32*128];         // 16KB
    int b = blockIdx.y; int px0 = blockIdx.x*128;
    int t = threadIdx.x;
    int pxt = t & 31, ocg = t >> 5;
    u64 acc[4][4];
    #pragma unroll
    for (int p=0;p<4;p++)
        #pragma unroll
        for (int j=0;j<4;j++) acc[p][j]=0ULL;

    const float* gb = g_g + (size_t)b*HFC*HW + px0;
    for (int kc=0;kc<4;kc++){
        __syncthreads();
        for (int idx=t; idx<32*128; idx+=256){
            int ii = idx>>7, p = idx&127;
            gs[idx] = gb[(size_t)(kc*32+ii)*HW + p];
        }
        __syncthreads();
        #pragma unroll 4
        for (int ii=0; ii<32; ii++){
            float4 xv = *(const float4*)&gs[ii*128 + pxt*4];
            u64 xp0 = pk(xv.x,xv.x), xp1 = pk(xv.y,xv.y);
            u64 xp2 = pk(xv.z,xv.z), xp3 = pk(xv.w,xv.w);
            const u64* wr = &g_wo[(kc*32+ii)*32 + ocg*4];
            #pragma unroll
            for (int j=0;j<4;j++){
                u64 w = __ldg(&wr[j]);
                fma2(acc[0][j], xp0, w);
                fma2(acc[1][j], xp1, w);
                fma2(acc[2][j], xp2, w);
                fma2(acc[3][j], xp3, w);
            }
        }
    }
    float* ob = out + (size_t)b*DIMC*HW + px0;
    #pragma unroll
    for (int j=0;j<4;j++){
        int jj = ocg*4 + j;
        float2 v0=upk(acc[0][j]), v1=upk(acc[1][j]), v2=upk(acc[2][j]), v3=upk(acc[3][j]);
        *(float4*)&ob[(size_t)(2*jj)*HW   + pxt*4] = make_float4(v0.x, v1.x, v2.x, v3.x);
        *(float4*)&ob[(size_t)(2*jj+1)*HW + pxt*4] = make_float4(v0.y, v1.y, v2.y, v3.y);
    }
}

// -----------------------------------------------------------------------------
extern "C" void kernel_launch(void* const* d_in, const int* in_sizes, int n_in,
                              void* d_out, int out_size){
    const float* x     = (const float*)d_in[0];
    const float* w_in  = (const float*)d_in[1];
    const float* w_dw  = (const float*)d_in[2];
    const float* filt  = (const float*)d_in[3];
    const float* w_out = (const float*)d_in[4];
    float* out = (float*)d_out;

    const int smem12 = (16*68 + 64*257 + 16*2060) * 4;   // 201984 B
    cudaFuncSetAttribute(k12_fused, cudaFuncAttributeMaxDynamicSharedMemorySize, smem12);

    k0_spectral<<<256, 256>>>(filt);
    k0_packw   <<<16, 256>>>(w_out);
    k12_fused  <<<dim3(16,32,4), 256, smem12>>>(x, w_in);
    k3_dwgelu  <<<dim3(16,128,4), 256>>>(w_dw);
    k4_outproj <<<dim3(512,4),    256>>>(out);
}

// round 10
// speedup vs baseline: 1.8146x; 1.8146x over previous
#include <cuda_runtime.h>
#include <math.h>

#define BATCH 4
#define DIMC  64
#define HFC   128
#define C2C   256
#define HH    256
#define WWC   256
#define HW    (HH*WWC)   // 65536

typedef unsigned int u32;
typedef unsigned long long u64;

// hs geometry (floats): ch-stride 1160, patch-stride 72 (conflict-engineered)
#define HS_CS 1160
#define HS_PS 72
// xs row stride
#define XS_S 136

// ---------------- scratch (device globals: allocation-free rule) -------------
__device__ float  g_u[(size_t)BATCH*C2C*HW];          // spectral output (268 MB)
__device__ float  g_g[(size_t)BATCH*HFC*HW];          // gated output    (134 MB)
__device__ float4 g_ga[(size_t)C2C*8*4*32];           // conv-G A-fragments (4 MB)
__device__ float4 g_wa[16*8*32];                      // w_in A-fragments
__device__ u64    g_wo[128*32];                       // packed w_out for K4

// ---------------- helpers ----------------------------------------------------
__device__ __forceinline__ u32 tf32b(float x){
    u32 r; asm("cvt.rna.tf32.f32 %0, %1;" : "=r"(r) : "f"(x)); return r;
}
__device__ __forceinline__ float tf32f(float x){ return __uint_as_float(tf32b(x)); }
__device__ __forceinline__ u32 bits(float x){ return __float_as_uint(x); }

__device__ __forceinline__ void mma8(float* d, u32 a0,u32 a1,u32 a2,u32 a3, u32 b0,u32 b1){
    asm("mma.sync.aligned.m16n8k8.row.col.f32.tf32.tf32.f32 "
        "{%0,%1,%2,%3},{%4,%5,%6,%7},{%8,%9},{%0,%1,%2,%3};"
        : "+f"(d[0]),"+f"(d[1]),"+f"(d[2]),"+f"(d[3])
        : "r"(a0),"r"(a1),"r"(a2),"r"(a3),"r"(b0),"r"(b1));
}

__device__ __forceinline__ u64 pk(float lo, float hi){
    u64 r; asm("mov.b64 %0, {%1,%2};" : "=l"(r) : "f"(lo), "f"(hi)); return r;
}
__device__ __forceinline__ float2 upk(u64 v){
    float2 r; asm("mov.b64 {%0,%1}, %2;" : "=f"(r.x), "=f"(r.y) : "l"(v)); return r;
}
__device__ __forceinline__ void fma2(u64& d, u64 a, u64 b){
    asm("fma.rn.f32x2 %0, %1, %2, %0;" : "+l"(d) : "l"(a), "l"(b));
}

// ---------------- K0: spectral filter -> conv-G MMA A-fragments --------------
// g_c[n1,n2] = (1/64) * sum_{k1,k2} G(k1,k2) cos(pi/4*(k1*n1+k2*n2)),
// G = Hermitian extension of F with symmetrization at k2 in {0,4}.
// Conv matrix Gm[n][m] = g[(n1-m1)&7][(n2-m2)&7];  u_patch = Gm @ h_patch.
// A-fragment (row-major M=64 x K=64, tiles kk,mt), per lane (lq=lane/4,la=lane%3..):
//   a0 = Gm[mt*16+lq][kk*8+la], a1 = +8 row, a2 = +4 col, a3 = both.
__global__ void k0_spectral(const float* __restrict__ filt){
    __shared__ float gs[64];
    int c = blockIdx.x, t = threadIdx.x;
    if (t < 64){
        int n1 = t >> 3, n2 = t & 7;
        const float* F = filt + c*40;   // [8][5]
        float s = 0.f;
        for (int k1=0;k1<8;k1++){
            for (int k2=0;k2<8;k2++){
                float Gv;
                if (k2>=1 && k2<=3)      Gv = F[k1*5+k2];
                else if (k2>=5)          Gv = F[((8-k1)&7)*5 + (8-k2)];
                else                     Gv = 0.5f*(F[k1*5+k2] + F[((8-k1)&7)*5 + k2]);
                int m = (k1*n1 + k2*n2) & 7;
                s += Gv * cospif(0.25f * (float)m);
            }
        }
        gs[t] = s * (1.f/64.f);
    }
    __syncthreads();
    for (int i=t; i<8*4*32; i+=256){
        int kk = i>>7, mt = (i>>5)&3, lane = i&31;
        int lq = lane>>2, la = lane&3;
        int n0 = mt*16+lq, n1r = n0+8;
        int m0 = kk*8+la,  m1c = m0+4;
        #define GM(n,m) gs[ ((((n)>>3)-((m)>>3))&7)*8 + ((((n)&7)-((m)&7))&7) ]
        g_ga[((size_t)(c*8+kk)*4 + mt)*32 + lane] =
            make_float4(tf32f(GM(n0,m0)), tf32f(GM(n1r,m0)),
                        tf32f(GM(n0,m1c)), tf32f(GM(n1r,m1c)));
        #undef GM
    }
}

// ---------------- K0b: pack w_in A-fragments + w_out pairs -------------------
__global__ void k0_packw(const float* __restrict__ w_in, const float* __restrict__ w_out){
    int idx = blockIdx.x*256 + threadIdx.x;      // 16*256 = 4096
    {
        int ocg = idx>>8, kk = (idx>>5)&7, lane = idx&31;
        int lq = lane>>2, la = lane&3;
        int o = ocg*16, k = kk*8;
        g_wa[idx] = make_float4(
            tf32f(w_in[(o+lq)*DIMC + k+la]),
            tf32f(w_in[(o+lq+8)*DIMC + k+la]),
            tf32f(w_in[(o+lq)*DIMC + k+la+4]),
            tf32f(w_in[(o+lq+8)*DIMC + k+la+4]));
    }
    if (idx < 128*32){
        int ii = idx >> 5, j = idx & 31;
        g_wo[idx] = pk(w_out[(2*j)*HFC + ii], w_out[(2*j+1)*HFC + ii]);
    }
}

// ---------------- K12: fused in-proj GEMM + spectral conv GEMM (tf32 MMA) ----
// Block: 16 channels x (8-row x 128-col strip = 16 patches). Grid (16,64,4),
// ocg innermost for x L2 reuse. 109KB smem -> 2 CTAs/SM.
__global__ __launch_bounds__(256, 2) void k12_fused(const float* __restrict__ x){
    extern __shared__ float sm[];
    float* xs = sm;                  // [64][XS_S]  35KB
    float* hs = sm + 64*XS_S;        // 16ch x 16p x 64m (strides HS_CS/HS_PS) 74KB
    int ocg = blockIdx.x;            // 16 channels: ocg*16 ..
    int s   = blockIdx.y;            // strip: 8 rows x 128 cols
    int b   = blockIdx.z;
    int t = threadIdx.x, lane = t & 31, w = t >> 5;
    int la = lane & 3, lq = lane >> 2;

    // W fragments (held in regs through phase 1)
    float4 wa[8];
    #pragma unroll
    for (int kk=0;kk<8;kk++) wa[kk] = g_wa[(ocg*8+kk)*32 + lane];

    int s8 = (s>>1)*8, cb = (s&1)*128;
    const float* xb = x + (size_t)b*DIMC*HW + (size_t)s8*WWC + cb;

    // ---------------- Phase 1: h = W @ x (per row of strip) ----------------
    int sc = t>>2, seg = t&3;        // staging map: 64 ch x 4 segs of 32 floats
    for (int r=0; r<8; r++){
        __syncthreads();
        {
            const float4* src = (const float4*)(xb + (size_t)sc*HW + r*WWC) + seg*8;
            float* dst = xs + sc*XS_S + seg*32;
            #pragma unroll
            for (int j=0;j<8;j++){
                float4 v = src[j];
                dst[j*4+0]=tf32f(v.x); dst[j*4+1]=tf32f(v.y);
                dst[j*4+2]=tf32f(v.z); dst[j*4+3]=tf32f(v.w);
            }
        }
        __syncthreads();
        #pragma unroll
        for (int nt=0;nt<2;nt++){
            int p = w*2 + nt;
            float d[4] = {0.f,0.f,0.f,0.f};
            #pragma unroll
            for (int kk=0;kk<8;kk++){
                u32 b0 = bits(xs[(kk*8+la)*XS_S + p*8 + lq]);
                u32 b1 = bits(xs[(kk*8+la+4)*XS_S + p*8 + lq]);
                mma8(d, bits(wa[kk].x),bits(wa[kk].y),bits(wa[kk].z),bits(wa[kk].w), b0,b1);
            }
            int m = r*8 + 2*la;
            *(float2*)&hs[lq*HS_CS     + p*HS_PS + m] = make_float2(tf32f(d[0]), tf32f(d[1]));
            *(float2*)&hs[(lq+8)*HS_CS + p*HS_PS + m] = make_float2(tf32f(d[2]), tf32f(d[3]));
        }
    }
    __syncthreads();

    // ---------------- Phase 2: u_patch = Gm @ h_patch (per channel) --------
    for (int ci=0; ci<2; ci++){
        int chl = w*2 + ci;
        const float4* ga = &g_ga[((size_t)((ocg*16+chl)*8))*4*32 + lane];
        float d[4][2][4];
        #pragma unroll
        for (int mt=0;mt<4;mt++)
            #pragma unroll
            for (int nt=0;nt<2;nt++){ d[mt][nt][0]=d[mt][nt][1]=d[mt][nt][2]=d[mt][nt][3]=0.f; }
        #pragma unroll
        for (int kk=0;kk<8;kk++){
            u32 b0[2], b1[2];
            #pragma unroll
            for (int nt=0;nt<2;nt++){
                b0[nt] = bits(hs[chl*HS_CS + (nt*8+lq)*HS_PS + kk*8+la]);
                b1[nt] = bits(hs[chl*HS_CS + (nt*8+lq)*HS_PS + kk*8+la+4]);
            }
            #pragma unroll
            for (int mt=0;mt<4;mt++){
                float4 a = ga[(kk*4+mt)*32];
                u32 a0=bits(a.x), a1=bits(a.y), a2=bits(a.z), a3=bits(a.w);
                mma8(d[mt][0], a0,a1,a2,a3, b0[0],b1[0]);
                mma8(d[mt][1], a0,a1,a2,a3, b0[1],b1[1]);
            }
        }
        float* ub = g_u + (size_t)(b*C2C + ocg*16 + chl)*HW + (size_t)s8*WWC + cb;
        #pragma unroll
        for (int mt=0;mt<4;mt++){
            #pragma unroll
            for (int nt=0;nt<2;nt++){
                int c0 = (nt*8 + 2*la)*8 + lq;
                ub[(2*mt)*WWC   + c0]     = d[mt][nt][0];
                ub[(2*mt)*WWC   + c0 + 8] = d[mt][nt][1];
                ub[(2*mt+1)*WWC + c0]     = d[mt][nt][2];
                ub[(2*mt+1)*WWC + c0 + 8] = d[mt][nt][3];
            }
        }
    }
}

// ---------------- K3: depthwise 3x3 (SAME) + exact GELU gate -----------------
__global__ __launch_bounds__(256) void k3_dwgelu(const float* __restrict__ w_dw){
    __shared__ float su[2][18][258];
    int yt = blockIdx.x, i = blockIdx.y, b = blockIdx.z;
    int t = threadIdx.x;
    int y0 = yt*16;
    const float* u1 = g_u + (size_t)(b*C2C + i)*HW;
    const float* u2 = g_u + (size_t)(b*C2C + i + HFC)*HW;
    for (int rr=0; rr<18; rr++){
        int y = y0 + rr - 1;
        bool ok = (y>=0 && y<HH);
        su[0][rr][t+1] = ok ? u1[y*WWC + t] : 0.f;
        su[1][rr][t+1] = ok ? u2[y*WWC + t] : 0.f;
    }
    if (t < 18){ su[0][t][0]=0.f; su[0][t][257]=0.f; su[1][t][0]=0.f; su[1][t][257]=0.f; }
    __syncthreads();
    float wA[9], wB[9];
    #pragma unroll
    for (int k=0;k<9;k++){ wA[k]=w_dw[i*9+k]; wB[k]=w_dw[(i+HFC)*9+k]; }
    float* gb = g_g + (size_t)(b*HFC + i)*HW;
    for (int r=0;r<16;r++){
        float d1=0.f, d2=0.f;
        #pragma unroll
        for (int dy=0;dy<3;dy++){
            #pragma unroll
            for (int dx=0;dx<3;dx++){
                d1 = fmaf(wA[dy*3+dx], su[0][r+dy][t+dx], d1);
                d2 = fmaf(wB[dy*3+dx], su[1][r+dy][t+dx], d2);
            }
        }
        float ge = 0.5f*d1*(1.f + erff(d1*0.70710678118654752f));
        gb[(y0+r)*WWC + t] = ge*d2;
    }
}

// ---------------- K4: out-projection (register-tiled FMA2 GEMM) --------------
__global__ __launch_bounds__(256) void k4_outproj(float* __restrict__ out){
    __shared__ float gs[32*128];         // 16KB
    int b = blockIdx.y; int px0 = blockIdx.x*128;
    int t = threadIdx.x;
    int pxt = t & 31, ocg = t >> 5;
    u64 acc[4][4];
    #pragma unroll
    for (int p=0;p<4;p++)
        #pragma unroll
        for (int j=0;j<4;j++) acc[p][j]=0ULL;

    const float* gb = g_g + (size_t)b*HFC*HW + px0;
    for (int kc=0;kc<4;kc++){
        __syncthreads();
        for (int idx=t; idx<32*128; idx+=256){
            int ii = idx>>7, p = idx&127;
            gs[idx] = gb[(size_t)(kc*32+ii)*HW + p];
        }
        __syncthreads();
        #pragma unroll 4
        for (int ii=0; ii<32; ii++){
            float4 xv = *(const float4*)&gs[ii*128 + pxt*4];
            u64 xp0 = pk(xv.x,xv.x), xp1 = pk(xv.y,xv.y);
            u64 xp2 = pk(xv.z,xv.z), xp3 = pk(xv.w,xv.w);
            const u64* wr = &g_wo[(kc*32+ii)*32 + ocg*4];
            #pragma unroll
            for (int j=0;j<4;j++){
                u64 w = __ldg(&wr[j]);
                fma2(acc[0][j], xp0, w);
                fma2(acc[1][j], xp1, w);
                fma2(acc[2][j], xp2, w);
                fma2(acc[3][j], xp3, w);
            }
        }
    }
    float* ob = out + (size_t)b*DIMC*HW + px0;
    #pragma unroll
    for (int j=0;j<4;j++){
        int jj = ocg*4 + j;
        float2 v0=upk(acc[0][j]), v1=upk(acc[1][j]), v2=upk(acc[2][j]), v3=upk(acc[3][j]);
        *(float4*)&ob[(size_t)(2*jj)*HW   + pxt*4] = make_float4(v0.x, v1.x, v2.x, v3.x);
        *(float4*)&ob[(size_t)(2*jj+1)*HW + pxt*4] = make_float4(v0.y, v1.y, v2.y, v3.y);
    }
}

// -----------------------------------------------------------------------------
extern "C" void kernel_launch(void* const* d_in, const int* in_sizes, int n_in,
                              void* d_out, int out_size){
    const float* x     = (const float*)d_in[0];
    const float* w_in  = (const float*)d_in[1];
    const float* w_dw  = (const float*)d_in[2];
    const float* filt  = (const float*)d_in[3];
    const float* w_out = (const float*)d_in[4];
    float* out = (float*)d_out;

    const int smem12 = (64*XS_S + 16*HS_CS) * 4;     // 35,? + 74,240 = 109,312 B
    cudaFuncSetAttribute(k12_fused, cudaFuncAttributeMaxDynamicSharedMemorySize, smem12);

    k0_spectral<<<256, 256>>>(filt);
    k0_packw   <<<16, 256>>>(w_in, w_out);
    k12_fused  <<<dim3(16,64,4), 256, smem12>>>(x);
    k3_dwgelu  <<<dim3(16,128,4), 256>>>(w_dw);
    k4_outproj <<<dim3(512,4),    256>>>(out);
}